// round 15
// baseline (speedup 1.0000x reference)
#include <cuda_runtime.h>
#include <cuda_bf16.h>
#include <cuda_fp16.h>
#include <math.h>

#define MAXN 50000
#define MAXE 800000
#define F1 64      // nfeat
#define F2 128     // nhid
#define F3 64      // nclass
#define EPS 1e-6f

// ---------------- packed f32x2 helpers (Blackwell FFMA2) ----------------
typedef unsigned long long u64;
__device__ __forceinline__ u64 pack2(float lo, float hi) {
    u64 r; asm("mov.b64 %0, {%1,%2};" : "=l"(r) : "f"(lo), "f"(hi)); return r;
}
__device__ __forceinline__ u64 fma2(u64 a, u64 b, u64 c) {
    u64 d; asm("fma.rn.f32x2 %0, %1, %2, %3;" : "=l"(d) : "l"(a), "l"(b), "l"(c)); return d;
}
__device__ __forceinline__ float2 unpack2(u64 v) {
    float2 f; asm("mov.b64 {%0,%1}, %2;" : "=f"(f.x), "=f"(f.y) : "l"(v)); return f;
}

// ---------------- scratch (no allocation allowed) ----------------
__device__ __align__(16) __half g_xh[MAXN * F1];    // 6.4 MB: x in fp16
__device__ __align__(16) __half g_t[MAXN * F3];     // 6.4 MB: relu(h)@W2 in fp16
__device__ int g_counts[MAXN];                       // zero-init; self-zeroing per call
__device__ int g_rowptr[MAXN + 1];
__device__ int g_aggs[64];                           // scan block aggregates
__device__ int g_flags[64];                          // zero-init; self-resetting
__device__ int g_done[1];                            // zero-init; self-resetting
__device__ __align__(4) unsigned char g_rank[MAXE];  // edge rank within dst bucket (<256)
__device__ int g_sorted_src[MAXE];                   // src ids grouped by dst

// ================= hist + x->fp16 convert (E == N*F1/4 == 800000) =================
__global__ void hist_convert_kernel(const int* __restrict__ dst, int* __restrict__ counts,
                                    unsigned char* __restrict__ rank,
                                    const float* __restrict__ x, __half* __restrict__ xh,
                                    int E, int total4)
{
    int i = blockIdx.x * blockDim.x + threadIdx.x;
    if (i < E)
        rank[i] = (unsigned char)atomicAdd(counts + __ldg(dst + i), 1);
    if (i < total4) {
        float4 v = ((const float4*)x)[i];
        __half2 p0 = __floats2half2_rn(v.x, v.y);
        __half2 p1 = __floats2half2_rn(v.z, v.w);
        uint2 packed;
        packed.x = *(unsigned int*)&p0;
        packed.y = *(unsigned int*)&p1;
        ((uint2*)xh)[i] = packed;
    }
}

// ================= one-pass scan (decoupled aggregate lookback) =================
__global__ void scan_kernel(int* __restrict__ counts, int* __restrict__ rowptr,
                            int* __restrict__ aggs, int* __restrict__ flags,
                            int* __restrict__ done, int N, int E)
{
    __shared__ int s[256];
    __shared__ int s2[64];
    __shared__ int block_prefix;
    int b = blockIdx.x, t = threadIdx.x;
    int base = b * 1024 + t * 4;
    int v[4]; int sum = 0;
    #pragma unroll
    for (int j = 0; j < 4; j++) {
        v[j] = (base + j < N) ? counts[base + j] : 0;
        if (base + j < N) counts[base + j] = 0;
        sum += v[j];
    }
    s[t] = sum;
    if (t < 64) s2[t] = 0;
    __syncthreads();
    #pragma unroll
    for (int off = 1; off < 256; off <<= 1) {
        int x = (t >= off) ? s[t - off] : 0;
        __syncthreads();
        s[t] += x;
        __syncthreads();
    }
    int run = s[t] - sum;

    if (t == 255) {
        aggs[b] = s[255];
        __threadfence();
        atomicExch(flags + b, 1);
    }
    int pre = 0;
    if (t < b) {
        while (atomicAdd(flags + t, 0) == 0) { }
        __threadfence();
        pre = atomicAdd(aggs + t, 0);
    }
    __syncthreads();
    if (t < b) s2[t] = pre;
    __syncthreads();
    if (t == 0) {
        int p = 0;
        #pragma unroll
        for (int i = 0; i < 64; i++) p += s2[i];
        block_prefix = p;
    }
    __syncthreads();

    run += block_prefix;
    #pragma unroll
    for (int j = 0; j < 4; j++) {
        if (base + j < N) rowptr[base + j] = run;
        run += v[j];
    }
    if (b == 0 && t == 0) rowptr[N] = E;

    if (t == 0) {
        int d = atomicAdd(done, 1);
        if (d == gridDim.x - 1) {
            for (int i = 0; i < gridDim.x; i++) flags[i] = 0;
            *done = 0;
        }
    }
}

// ATOMIC-FREE scatter: position = rowptr[dst] + rank. 4 edges/thread.
__global__ void scatter_kernel(const int* __restrict__ src, const int* __restrict__ dst,
                               const int* __restrict__ rowptr,
                               const unsigned char* __restrict__ rank,
                               int* __restrict__ sorted_src, int E)
{
    int i0 = (blockIdx.x * blockDim.x + threadIdx.x) * 4;
    if (i0 + 3 < E) {
        int4 d = *(const int4*)(dst + i0);
        int4 s = *(const int4*)(src + i0);
        uchar4 r = *(const uchar4*)(rank + i0);
        sorted_src[__ldg(rowptr + d.x) + r.x] = s.x;
        sorted_src[__ldg(rowptr + d.y) + r.y] = s.y;
        sorted_src[__ldg(rowptr + d.z) + r.z] = s.z;
        sorted_src[__ldg(rowptr + d.w) + r.w] = s.w;
    } else {
        for (int i = i0; i < E; i++)
            sorted_src[__ldg(rowptr + __ldg(dst + i)) + rank[i]] = __ldg(src + i);
    }
}

// ================= Fused: gather-1 + GEMM1 + relu + GEMM2, 32-node tile =================
// smem 40 KB: Ws[64][128] fp32 (W1, rows 0..31 later reused as Hs) + As[32][64]
// (mean tile, later 32-row W2 chunks). Lower regs + smem -> ~5 blocks/SM.
__global__ __launch_bounds__(256) void fused12_kernel(const __half* __restrict__ xh,
                                                      const int* __restrict__ rowptr,
                                                      const int* __restrict__ sorted_src,
                                                      const float* __restrict__ W1,
                                                      const float* __restrict__ b1,
                                                      const float* __restrict__ W2,
                                                      __half* __restrict__ t,
                                                      int N)
{
    __shared__ float sbuf[64 * 128 + 32 * 64];   // 40 KB
    float (*Ws)[128] = (float(*)[128])sbuf;                  // W1; rows 0..31 -> Hs
    float (*As)[64]  = (float(*)[64])(sbuf + 64 * 128);      // mean tile / W2 chunks

    int tid = threadIdx.x;
    int node0 = blockIdx.x * 32;
    int wid = tid >> 5, lane = tid & 31;
    int grp = lane >> 3, sl = lane & 7;          // 4 groups of 8 lanes

    // ---- A: load W1 (2048 float4, 8/thread) ----
    #pragma unroll
    for (int i = 0; i < 8; i++) {
        int lin = tid + i * 256;
        ((float4*)Ws)[lin] = ((const float4*)W1)[lin];
    }

    // ---- A: gather means, 8 warps x 4 rows = 32 rows, one pass ----
    const uint4* x4 = (const uint4*)xh;          // 8 uint4 per 64-half row
    {
        int row = wid * 4 + grp;
        int node = node0 + row;
        float acc[8];
        #pragma unroll
        for (int i = 0; i < 8; i++) acc[i] = 0.f;
        int beg = 0, end = 0;
        if (node < N) { beg = __ldg(rowptr + node); end = __ldg(rowptr + node + 1); }
        for (int e = beg; e < end; e += 4) {
            int s[4];
            #pragma unroll
            for (int j = 0; j < 4; j++)
                s[j] = __ldg(sorted_src + min(e + j, end - 1));
            uint4 raw[4];
            #pragma unroll
            for (int j = 0; j < 4; j++)
                raw[j] = x4[s[j] * 8 + sl];
            #pragma unroll
            for (int j = 0; j < 4; j++)
                if (e + j < end) {
                    float2 a = __half22float2(*(__half2*)&raw[j].x);
                    float2 b = __half22float2(*(__half2*)&raw[j].y);
                    float2 c = __half22float2(*(__half2*)&raw[j].z);
                    float2 d = __half22float2(*(__half2*)&raw[j].w);
                    acc[0] += a.x; acc[1] += a.y;
                    acc[2] += b.x; acc[3] += b.y;
                    acc[4] += c.x; acc[5] += c.y;
                    acc[6] += d.x; acc[7] += d.y;
                }
        }
        float inv = 1.0f / ((float)(end - beg) + EPS);
        #pragma unroll
        for (int i = 0; i < 8; i++) acc[i] *= inv;
        *(float4*)&As[row][sl * 8]     = make_float4(acc[0], acc[1], acc[2], acc[3]);
        *(float4*)&As[row][sl * 8 + 4] = make_float4(acc[4], acc[5], acc[6], acc[7]);
    }
    __syncthreads();

    // ---- B: GEMM1 (32x128), 4 rows x 4 cols/thread, f32x2 packed ----
    int tx = tid & 31, ty = tid >> 5;
    int col0 = tx * 4, row0 = ty * 4;
    float4 bias = *(const float4*)(b1 + col0);
    u64 accL[4], accH[4];
    u64 biasL = pack2(bias.x, bias.y), biasH = pack2(bias.z, bias.w);
    #pragma unroll
    for (int r = 0; r < 4; r++) { accL[r] = biasL; accH[r] = biasH; }

    #pragma unroll 4
    for (int k = 0; k < 64; k++) {
        float4 w = *(float4*)&Ws[k][col0];
        u64 wL = pack2(w.x, w.y), wH = pack2(w.z, w.w);
        #pragma unroll
        for (int r = 0; r < 4; r++) {
            float m = As[row0 + r][k];
            u64 mm = pack2(m, m);
            accL[r] = fma2(mm, wL, accL[r]);
            accH[r] = fma2(mm, wH, accH[r]);
        }
    }
    __syncthreads();     // S1: everyone done reading Ws(W1) / As(mean)

    // ---- C: relu -> Hs (Ws rows 0..31) ----
    #pragma unroll
    for (int r = 0; r < 4; r++) {
        float2 lo = unpack2(accL[r]), hi = unpack2(accH[r]);
        float4 o;
        o.x = fmaxf(lo.x, 0.f);
        o.y = fmaxf(lo.y, 0.f);
        o.z = fmaxf(hi.x, 0.f);
        o.w = fmaxf(hi.y, 0.f);
        *(float4*)&Ws[row0 + r][col0] = o;
    }

    // ---- C: GEMM2 (32x128 @ 128x64), 2 rows x 4 cols/thread, 4 K-chunks of 32 ----
    int tx2 = tid & 15, ty2 = tid >> 4;
    int c0 = tx2 * 4, r0 = ty2 * 2;
    u64 acc2L[2], acc2H[2];
    u64 zz = pack2(0.f, 0.f);
    #pragma unroll
    for (int r = 0; r < 2; r++) { acc2L[r] = zz; acc2H[r] = zz; }

    #pragma unroll
    for (int c = 0; c < 4; c++) {
        __syncthreads();         // prev chunk reads done; (c==0) also publishes Hs
        // load W2 rows c*32..c*32+31 (512 float4, 2/thread) into As region
        #pragma unroll
        for (int i = 0; i < 2; i++) {
            int lin = tid + i * 256;
            ((float4*)As)[lin] = ((const float4*)W2)[c * 512 + lin];
        }
        __syncthreads();
        #pragma unroll 4
        for (int k = 0; k < 32; k++) {
            float4 w = *(float4*)&As[k][c0];
            u64 wL = pack2(w.x, w.y), wH = pack2(w.z, w.w);
            #pragma unroll
            for (int r = 0; r < 2; r++) {
                float m = Ws[r0 + r][c * 32 + k];
                u64 mm = pack2(m, m);
                acc2L[r] = fma2(mm, wL, acc2L[r]);
                acc2H[r] = fma2(mm, wH, acc2H[r]);
            }
        }
    }

    #pragma unroll
    for (int r = 0; r < 2; r++) {
        int node = node0 + r0 + r;
        if (node < N) {
            float2 lo = unpack2(acc2L[r]), hi = unpack2(acc2H[r]);
            __half2 p0 = __floats2half2_rn(lo.x, lo.y);
            __half2 p1 = __floats2half2_rn(hi.x, hi.y);
            uint2 packed;
            packed.x = *(unsigned int*)&p0;
            packed.y = *(unsigned int*)&p1;
            ((uint2*)t)[node * 16 + tx2] = packed;   // 16 uint2 per 64-half row
        }
    }
}

// ================= gather-2 (fp16 t) + bias + log_softmax =================
__global__ __launch_bounds__(256) void gather2_final_kernel(const __half* __restrict__ t,
                                                            const int* __restrict__ rowptr,
                                                            const int* __restrict__ sorted_src,
                                                            const float* __restrict__ b2,
                                                            float* __restrict__ out,
                                                            int N)
{
    int tid = threadIdx.x;
    int wid = tid >> 5, lane = tid & 31;
    int grp = lane >> 3, sl = lane & 7;
    int node = blockIdx.x * 32 + wid * 4 + grp;
    if (node >= N) return;

    const uint4* t4 = (const uint4*)t;   // 8 uint4 per 64-half row

    int beg = __ldg(rowptr + node);
    int end = __ldg(rowptr + node + 1);
    float acc[8];
    #pragma unroll
    for (int i = 0; i < 8; i++) acc[i] = 0.f;
    for (int e = beg; e < end; e += 4) {
        int s[4];
        #pragma unroll
        for (int j = 0; j < 4; j++)
            s[j] = __ldg(sorted_src + min(e + j, end - 1));
        uint4 raw[4];
        #pragma unroll
        for (int j = 0; j < 4; j++)
            raw[j] = t4[s[j] * 8 + sl];
        #pragma unroll
        for (int j = 0; j < 4; j++)
            if (e + j < end) {
                float2 a = __half22float2(*(__half2*)&raw[j].x);
                float2 b = __half22float2(*(__half2*)&raw[j].y);
                float2 c = __half22float2(*(__half2*)&raw[j].z);
                float2 d = __half22float2(*(__half2*)&raw[j].w);
                acc[0] += a.x; acc[1] += a.y;
                acc[2] += b.x; acc[3] += b.y;
                acc[4] += c.x; acc[5] += c.y;
                acc[6] += d.x; acc[7] += d.y;
            }
    }
    float inv = 1.0f / ((float)(end - beg) + EPS);
    float4 bb0 = ((const float4*)b2)[sl * 2];
    float4 bb1 = ((const float4*)b2)[sl * 2 + 1];
    float v[8];
    v[0] = acc[0] * inv + bb0.x;
    v[1] = acc[1] * inv + bb0.y;
    v[2] = acc[2] * inv + bb0.z;
    v[3] = acc[3] * inv + bb0.w;
    v[4] = acc[4] * inv + bb1.x;
    v[5] = acc[5] * inv + bb1.y;
    v[6] = acc[6] * inv + bb1.z;
    v[7] = acc[7] * inv + bb1.w;

    float m = v[0];
    #pragma unroll
    for (int i = 1; i < 8; i++) m = fmaxf(m, v[i]);
    #pragma unroll
    for (int o = 4; o > 0; o >>= 1)
        m = fmaxf(m, __shfl_xor_sync(0xffffffffu, m, o));
    float s = 0.f;
    #pragma unroll
    for (int i = 0; i < 8; i++) s += expf(v[i] - m);
    #pragma unroll
    for (int o = 4; o > 0; o >>= 1)
        s += __shfl_xor_sync(0xffffffffu, s, o);
    float l = m + logf(s);

    float4 o0 = make_float4(v[0] - l, v[1] - l, v[2] - l, v[3] - l);
    float4 o1 = make_float4(v[4] - l, v[5] - l, v[6] - l, v[7] - l);
    ((float4*)out)[node * 16 + sl * 2]     = o0;
    ((float4*)out)[node * 16 + sl * 2 + 1] = o1;
}

extern "C" void kernel_launch(void* const* d_in, const int* in_sizes, int n_in,
                              void* d_out, int out_size)
{
    const float* x   = (const float*)d_in[0];
    const int*   src = (const int*)d_in[1];
    const int*   dst = (const int*)d_in[2];
    const float* W1  = (const float*)d_in[3];
    const float* b1  = (const float*)d_in[4];
    const float* W2  = (const float*)d_in[5];
    const float* b2  = (const float*)d_in[6];
    float* out = (float*)d_out;

    int N = in_sizes[0] / F1;
    int E = in_sizes[1];

    __half *t, *xh;
    int *counts, *rowptr, *aggs, *flags, *done, *sorted_src;
    unsigned char *rank;
    cudaGetSymbolAddress((void**)&t, g_t);
    cudaGetSymbolAddress((void**)&xh, g_xh);
    cudaGetSymbolAddress((void**)&counts, g_counts);
    cudaGetSymbolAddress((void**)&rowptr, g_rowptr);
    cudaGetSymbolAddress((void**)&aggs, g_aggs);
    cudaGetSymbolAddress((void**)&flags, g_flags);
    cudaGetSymbolAddress((void**)&done, g_done);
    cudaGetSymbolAddress((void**)&rank, g_rank);
    cudaGetSymbolAddress((void**)&sorted_src, g_sorted_src);

    // ---- 1: hist + x->fp16 (counts zero on entry; scan re-zeroes) ----
    int total4 = (N * F1) / 4;
    int w = max(E, total4);
    hist_convert_kernel<<<(w + 255) / 256, 256, 0, 0>>>(dst, counts, rank, x, xh, E, total4);

    // ---- 2: one-pass scan -> final rowptr ----
    int nb = (N + 1023) / 1024;
    scan_kernel<<<nb, 256, 0, 0>>>(counts, rowptr, aggs, flags, done, N, E);

    // ---- 3: atomic-free scatter ----
    int et = (E + 3) / 4;
    scatter_kernel<<<(et + 255) / 256, 256, 0, 0>>>(src, dst, rowptr, rank, sorted_src, E);

    // ---- 4: gather(mean, fp16) -> W1+b1+relu -> @W2 -> t (fp16), 32-node tiles ----
    fused12_kernel<<<(N + 31) / 32, 256, 0, 0>>>(xh, rowptr, sorted_src, W1, b1, W2, t, N);

    // ---- 5: gather(mean, fp16) + b2 + log_softmax ----
    gather2_final_kernel<<<(N + 31) / 32, 256, 0, 0>>>(t, rowptr, sorted_src, b2, out, N);
}

// round 16
// speedup vs baseline: 1.1765x; 1.1765x over previous
#include <cuda_runtime.h>
#include <cuda_bf16.h>
#include <cuda_fp16.h>
#include <math.h>

#define MAXN 50000
#define MAXE 800000
#define F1 64      // nfeat
#define F2 128     // nhid
#define F3 64      // nclass
#define EPS 1e-6f

// ---------------- packed f32x2 helpers (Blackwell FFMA2) ----------------
typedef unsigned long long u64;
__device__ __forceinline__ u64 pack2(float lo, float hi) {
    u64 r; asm("mov.b64 %0, {%1,%2};" : "=l"(r) : "f"(lo), "f"(hi)); return r;
}
__device__ __forceinline__ u64 fma2(u64 a, u64 b, u64 c) {
    u64 d; asm("fma.rn.f32x2 %0, %1, %2, %3;" : "=l"(d) : "l"(a), "l"(b), "l"(c)); return d;
}
__device__ __forceinline__ float2 unpack2(u64 v) {
    float2 f; asm("mov.b64 {%0,%1}, %2;" : "=f"(f.x), "=f"(f.y) : "l"(v)); return f;
}

// ---------------- scratch (no allocation allowed) ----------------
__device__ __align__(16) __half g_xh[MAXN * F1];    // 6.4 MB: x in fp16
__device__ __align__(16) __half g_t[MAXN * F3];     // 6.4 MB: relu(h)@W2 in fp16
__device__ int g_counts[MAXN];                       // zero-init; self-zeroing per call
__device__ int g_rowptr[MAXN + 1];
__device__ int g_aggs[64];                           // scan block aggregates
__device__ int g_flags[64];                          // zero-init; self-resetting
__device__ int g_done[1];                            // zero-init; self-resetting
__device__ __align__(4) unsigned char g_rank[MAXE];  // edge rank within dst bucket (<256)
__device__ int g_sorted_src[MAXE];                   // src ids grouped by dst

// ================= hist + x->fp16 convert (E == N*F1/4 == 800000) =================
__global__ void hist_convert_kernel(const int* __restrict__ dst, int* __restrict__ counts,
                                    unsigned char* __restrict__ rank,
                                    const float* __restrict__ x, __half* __restrict__ xh,
                                    int E, int total4)
{
    int i = blockIdx.x * blockDim.x + threadIdx.x;
    if (i < E)
        rank[i] = (unsigned char)atomicAdd(counts + __ldg(dst + i), 1);
    if (i < total4) {
        float4 v = ((const float4*)x)[i];
        __half2 p0 = __floats2half2_rn(v.x, v.y);
        __half2 p1 = __floats2half2_rn(v.z, v.w);
        uint2 packed;
        packed.x = *(unsigned int*)&p0;
        packed.y = *(unsigned int*)&p1;
        ((uint2*)xh)[i] = packed;
    }
}

// ================= one-pass scan (decoupled aggregate lookback) =================
__global__ void scan_kernel(int* __restrict__ counts, int* __restrict__ rowptr,
                            int* __restrict__ aggs, int* __restrict__ flags,
                            int* __restrict__ done, int N, int E)
{
    __shared__ int s[256];
    __shared__ int s2[64];
    __shared__ int block_prefix;
    int b = blockIdx.x, t = threadIdx.x;
    int base = b * 1024 + t * 4;
    int v[4]; int sum = 0;
    #pragma unroll
    for (int j = 0; j < 4; j++) {
        v[j] = (base + j < N) ? counts[base + j] : 0;
        if (base + j < N) counts[base + j] = 0;
        sum += v[j];
    }
    s[t] = sum;
    if (t < 64) s2[t] = 0;
    __syncthreads();
    #pragma unroll
    for (int off = 1; off < 256; off <<= 1) {
        int x = (t >= off) ? s[t - off] : 0;
        __syncthreads();
        s[t] += x;
        __syncthreads();
    }
    int run = s[t] - sum;

    if (t == 255) {
        aggs[b] = s[255];
        __threadfence();
        atomicExch(flags + b, 1);
    }
    int pre = 0;
    if (t < b) {
        while (atomicAdd(flags + t, 0) == 0) { }
        __threadfence();
        pre = atomicAdd(aggs + t, 0);
    }
    __syncthreads();
    if (t < b) s2[t] = pre;
    __syncthreads();
    if (t == 0) {
        int p = 0;
        #pragma unroll
        for (int i = 0; i < 64; i++) p += s2[i];
        block_prefix = p;
    }
    __syncthreads();

    run += block_prefix;
    #pragma unroll
    for (int j = 0; j < 4; j++) {
        if (base + j < N) rowptr[base + j] = run;
        run += v[j];
    }
    if (b == 0 && t == 0) rowptr[N] = E;

    if (t == 0) {
        int d = atomicAdd(done, 1);
        if (d == gridDim.x - 1) {
            for (int i = 0; i < gridDim.x; i++) flags[i] = 0;
            *done = 0;
        }
    }
}

// ATOMIC-FREE scatter: position = rowptr[dst] + rank. 4 edges/thread.
__global__ void scatter_kernel(const int* __restrict__ src, const int* __restrict__ dst,
                               const int* __restrict__ rowptr,
                               const unsigned char* __restrict__ rank,
                               int* __restrict__ sorted_src, int E)
{
    int i0 = (blockIdx.x * blockDim.x + threadIdx.x) * 4;
    if (i0 + 3 < E) {
        int4 d = *(const int4*)(dst + i0);
        int4 s = *(const int4*)(src + i0);
        uchar4 r = *(const uchar4*)(rank + i0);
        sorted_src[__ldg(rowptr + d.x) + r.x] = s.x;
        sorted_src[__ldg(rowptr + d.y) + r.y] = s.y;
        sorted_src[__ldg(rowptr + d.z) + r.z] = s.z;
        sorted_src[__ldg(rowptr + d.w) + r.w] = s.w;
    } else {
        for (int i = i0; i < E; i++)
            sorted_src[__ldg(rowptr + __ldg(dst + i)) + rank[i]] = __ldg(src + i);
    }
}

// ================= Fused: gather-1 + GEMM1 + relu + GEMM2 (R12 base) =================
// 64-node tile, 48 KB smem, k-PAIR GEMM inner loops (2-k weight preload + float2
// broadcast m-loads): ~33% fewer LDS wavefronts vs R12, ~8 fewer live regs vs R13.
__global__ __launch_bounds__(256, 4) void fused12_kernel(const __half* __restrict__ xh,
                                                         const int* __restrict__ rowptr,
                                                         const int* __restrict__ sorted_src,
                                                         const float* __restrict__ W1,
                                                         const float* __restrict__ b1,
                                                         const float* __restrict__ W2,
                                                         __half* __restrict__ t,
                                                         int N)
{
    __shared__ float sbuf[64 * 128 + 64 * 64];   // 48 KB
    float (*Ws)[128] = (float(*)[128])sbuf;                  // W1, then Hs
    float (*As)[64]  = (float(*)[64])(sbuf + 64 * 128);      // mean tile, then W2 chunks

    int tid = threadIdx.x;
    int node0 = blockIdx.x * 64;
    int wid = tid >> 5, lane = tid & 31;
    int grp = lane >> 3, sl = lane & 7;          // 4 groups of 8 lanes

    // ---- A: load W1 (2048 float4, 8/thread) ----
    #pragma unroll
    for (int i = 0; i < 8; i++) {
        int lin = tid + i * 256;
        ((float4*)Ws)[lin] = ((const float4*)W1)[lin];
    }

    // ---- A: gather means. 2 passes x (8 warps x 4 rows) = 64 rows ----
    const uint4* x4 = (const uint4*)xh;          // 8 uint4 per 64-half row
    #pragma unroll
    for (int pass = 0; pass < 2; pass++) {
        int row = pass * 32 + wid * 4 + grp;
        int node = node0 + row;
        float acc[8];
        #pragma unroll
        for (int i = 0; i < 8; i++) acc[i] = 0.f;
        int beg = 0, end = 0;
        if (node < N) { beg = __ldg(rowptr + node); end = __ldg(rowptr + node + 1); }
        for (int e = beg; e < end; e += 4) {
            int s[4];
            #pragma unroll
            for (int j = 0; j < 4; j++)
                s[j] = __ldg(sorted_src + min(e + j, end - 1));
            uint4 raw[4];
            #pragma unroll
            for (int j = 0; j < 4; j++)
                raw[j] = x4[s[j] * 8 + sl];
            #pragma unroll
            for (int j = 0; j < 4; j++)
                if (e + j < end) {
                    float2 a = __half22float2(*(__half2*)&raw[j].x);
                    float2 b = __half22float2(*(__half2*)&raw[j].y);
                    float2 c = __half22float2(*(__half2*)&raw[j].z);
                    float2 d = __half22float2(*(__half2*)&raw[j].w);
                    acc[0] += a.x; acc[1] += a.y;
                    acc[2] += b.x; acc[3] += b.y;
                    acc[4] += c.x; acc[5] += c.y;
                    acc[6] += d.x; acc[7] += d.y;
                }
        }
        float inv = 1.0f / ((float)(end - beg) + EPS);
        #pragma unroll
        for (int i = 0; i < 8; i++) acc[i] *= inv;
        *(float4*)&As[row][sl * 8]     = make_float4(acc[0], acc[1], acc[2], acc[3]);
        *(float4*)&As[row][sl * 8 + 4] = make_float4(acc[4], acc[5], acc[6], acc[7]);
    }
    __syncthreads();

    // ---- B: GEMM1 (64x128), 8 rows x 4 cols/thread, k-pair ----
    int tx = tid & 31, ty = tid >> 5;
    int col0 = tx * 4, row0 = ty * 8;
    float4 bias = *(const float4*)(b1 + col0);
    u64 accL[8], accH[8];
    u64 biasL = pack2(bias.x, bias.y), biasH = pack2(bias.z, bias.w);
    #pragma unroll
    for (int r = 0; r < 8; r++) { accL[r] = biasL; accH[r] = biasH; }

    #pragma unroll 2
    for (int k2 = 0; k2 < 64; k2 += 2) {
        float4 w0 = *(float4*)&Ws[k2][col0];
        float4 w1 = *(float4*)&Ws[k2 + 1][col0];
        u64 w0L = pack2(w0.x, w0.y), w0H = pack2(w0.z, w0.w);
        u64 w1L = pack2(w1.x, w1.y), w1H = pack2(w1.z, w1.w);
        #pragma unroll
        for (int r = 0; r < 8; r++) {
            float2 m2 = *(float2*)&As[row0 + r][k2];   // broadcast, 1 wf / 2 k
            u64 mm0 = pack2(m2.x, m2.x);
            accL[r] = fma2(mm0, w0L, accL[r]);
            accH[r] = fma2(mm0, w0H, accH[r]);
            u64 mm1 = pack2(m2.y, m2.y);
            accL[r] = fma2(mm1, w1L, accL[r]);
            accH[r] = fma2(mm1, w1H, accH[r]);
        }
    }
    __syncthreads();     // S1: everyone done reading Ws/As

    // ---- C: relu -> Hs (Ws storage); load W2 chunk 0 into As ----
    #pragma unroll
    for (int r = 0; r < 8; r++) {
        float2 lo = unpack2(accL[r]), hi = unpack2(accH[r]);
        float4 o;
        o.x = fmaxf(lo.x, 0.f);
        o.y = fmaxf(lo.y, 0.f);
        o.z = fmaxf(hi.x, 0.f);
        o.w = fmaxf(hi.y, 0.f);
        *(float4*)&Ws[row0 + r][col0] = o;
    }
    #pragma unroll
    for (int i = 0; i < 4; i++) {
        int lin = tid + i * 256;
        ((float4*)As)[lin] = ((const float4*)W2)[lin];          // chunk 0
    }

    int tx2 = tid & 15, ty2 = tid >> 4;
    int c0 = tx2 * 4, r0 = ty2 * 4;
    u64 acc2L[4], acc2H[4];
    u64 zz = pack2(0.f, 0.f);
    #pragma unroll
    for (int r = 0; r < 4; r++) { acc2L[r] = zz; acc2H[r] = zz; }

    #pragma unroll
    for (int c = 0; c < 2; c++) {
        if (c == 1) {
            __syncthreads();     // S3: chunk-0 reads done
            #pragma unroll
            for (int i = 0; i < 4; i++) {
                int lin = tid + i * 256;
                ((float4*)As)[lin] = ((const float4*)W2)[1024 + lin];   // chunk 1
            }
        }
        __syncthreads();         // S2 / S4
        #pragma unroll 2
        for (int k2 = 0; k2 < 64; k2 += 2) {
            float4 w0 = *(float4*)&As[k2][c0];
            float4 w1 = *(float4*)&As[k2 + 1][c0];
            u64 w0L = pack2(w0.x, w0.y), w0H = pack2(w0.z, w0.w);
            u64 w1L = pack2(w1.x, w1.y), w1H = pack2(w1.z, w1.w);
            #pragma unroll
            for (int r = 0; r < 4; r++) {
                float2 m2 = *(float2*)&Ws[r0 + r][c * 64 + k2];
                u64 mm0 = pack2(m2.x, m2.x);
                acc2L[r] = fma2(mm0, w0L, acc2L[r]);
                acc2H[r] = fma2(mm0, w0H, acc2H[r]);
                u64 mm1 = pack2(m2.y, m2.y);
                acc2L[r] = fma2(mm1, w1L, acc2L[r]);
                acc2H[r] = fma2(mm1, w1H, acc2H[r]);
            }
        }
    }

    #pragma unroll
    for (int r = 0; r < 4; r++) {
        int node = node0 + r0 + r;
        if (node < N) {
            float2 lo = unpack2(acc2L[r]), hi = unpack2(acc2H[r]);
            __half2 p0 = __floats2half2_rn(lo.x, lo.y);
            __half2 p1 = __floats2half2_rn(hi.x, hi.y);
            uint2 packed;
            packed.x = *(unsigned int*)&p0;
            packed.y = *(unsigned int*)&p1;
            ((uint2*)t)[node * 16 + tx2] = packed;   // 16 uint2 per 64-half row
        }
    }
}

// ================= gather-2 (fp16 t) + bias + log_softmax =================
__global__ __launch_bounds__(256) void gather2_final_kernel(const __half* __restrict__ t,
                                                            const int* __restrict__ rowptr,
                                                            const int* __restrict__ sorted_src,
                                                            const float* __restrict__ b2,
                                                            float* __restrict__ out,
                                                            int N)
{
    int tid = threadIdx.x;
    int wid = tid >> 5, lane = tid & 31;
    int grp = lane >> 3, sl = lane & 7;
    int node = blockIdx.x * 32 + wid * 4 + grp;
    if (node >= N) return;

    const uint4* t4 = (const uint4*)t;   // 8 uint4 per 64-half row

    int beg = __ldg(rowptr + node);
    int end = __ldg(rowptr + node + 1);
    float acc[8];
    #pragma unroll
    for (int i = 0; i < 8; i++) acc[i] = 0.f;
    for (int e = beg; e < end; e += 4) {
        int s[4];
        #pragma unroll
        for (int j = 0; j < 4; j++)
            s[j] = __ldg(sorted_src + min(e + j, end - 1));
        uint4 raw[4];
        #pragma unroll
        for (int j = 0; j < 4; j++)
            raw[j] = t4[s[j] * 8 + sl];
        #pragma unroll
        for (int j = 0; j < 4; j++)
            if (e + j < end) {
                float2 a = __half22float2(*(__half2*)&raw[j].x);
                float2 b = __half22float2(*(__half2*)&raw[j].y);
                float2 c = __half22float2(*(__half2*)&raw[j].z);
                float2 d = __half22float2(*(__half2*)&raw[j].w);
                acc[0] += a.x; acc[1] += a.y;
                acc[2] += b.x; acc[3] += b.y;
                acc[4] += c.x; acc[5] += c.y;
                acc[6] += d.x; acc[7] += d.y;
            }
    }
    float inv = 1.0f / ((float)(end - beg) + EPS);
    float4 bb0 = ((const float4*)b2)[sl * 2];
    float4 bb1 = ((const float4*)b2)[sl * 2 + 1];
    float v[8];
    v[0] = acc[0] * inv + bb0.x;
    v[1] = acc[1] * inv + bb0.y;
    v[2] = acc[2] * inv + bb0.z;
    v[3] = acc[3] * inv + bb0.w;
    v[4] = acc[4] * inv + bb1.x;
    v[5] = acc[5] * inv + bb1.y;
    v[6] = acc[6] * inv + bb1.z;
    v[7] = acc[7] * inv + bb1.w;

    float m = v[0];
    #pragma unroll
    for (int i = 1; i < 8; i++) m = fmaxf(m, v[i]);
    #pragma unroll
    for (int o = 4; o > 0; o >>= 1)
        m = fmaxf(m, __shfl_xor_sync(0xffffffffu, m, o));
    float s = 0.f;
    #pragma unroll
    for (int i = 0; i < 8; i++) s += expf(v[i] - m);
    #pragma unroll
    for (int o = 4; o > 0; o >>= 1)
        s += __shfl_xor_sync(0xffffffffu, s, o);
    float l = m + logf(s);

    float4 o0 = make_float4(v[0] - l, v[1] - l, v[2] - l, v[3] - l);
    float4 o1 = make_float4(v[4] - l, v[5] - l, v[6] - l, v[7] - l);
    ((float4*)out)[node * 16 + sl * 2]     = o0;
    ((float4*)out)[node * 16 + sl * 2 + 1] = o1;
}

extern "C" void kernel_launch(void* const* d_in, const int* in_sizes, int n_in,
                              void* d_out, int out_size)
{
    const float* x   = (const float*)d_in[0];
    const int*   src = (const int*)d_in[1];
    const int*   dst = (const int*)d_in[2];
    const float* W1  = (const float*)d_in[3];
    const float* b1  = (const float*)d_in[4];
    const float* W2  = (const float*)d_in[5];
    const float* b2  = (const float*)d_in[6];
    float* out = (float*)d_out;

    int N = in_sizes[0] / F1;
    int E = in_sizes[1];

    __half *t, *xh;
    int *counts, *rowptr, *aggs, *flags, *done, *sorted_src;
    unsigned char *rank;
    cudaGetSymbolAddress((void**)&t, g_t);
    cudaGetSymbolAddress((void**)&xh, g_xh);
    cudaGetSymbolAddress((void**)&counts, g_counts);
    cudaGetSymbolAddress((void**)&rowptr, g_rowptr);
    cudaGetSymbolAddress((void**)&aggs, g_aggs);
    cudaGetSymbolAddress((void**)&flags, g_flags);
    cudaGetSymbolAddress((void**)&done, g_done);
    cudaGetSymbolAddress((void**)&rank, g_rank);
    cudaGetSymbolAddress((void**)&sorted_src, g_sorted_src);

    // ---- 1: hist + x->fp16 (counts zero on entry; scan re-zeroes) ----
    int total4 = (N * F1) / 4;
    int w = max(E, total4);
    hist_convert_kernel<<<(w + 255) / 256, 256, 0, 0>>>(dst, counts, rank, x, xh, E, total4);

    // ---- 2: one-pass scan -> final rowptr ----
    int nb = (N + 1023) / 1024;
    scan_kernel<<<nb, 256, 0, 0>>>(counts, rowptr, aggs, flags, done, N, E);

    // ---- 3: atomic-free scatter ----
    int et = (E + 3) / 4;
    scatter_kernel<<<(et + 255) / 256, 256, 0, 0>>>(src, dst, rowptr, rank, sorted_src, E);

    // ---- 4: gather(mean, fp16) -> W1+b1+relu -> @W2 -> t (fp16), 64-node tiles ----
    fused12_kernel<<<(N + 63) / 64, 256, 0, 0>>>(xh, rowptr, sorted_src, W1, b1, W2, t, N);

    // ---- 5: gather(mean, fp16) + b2 + log_softmax ----
    gather2_final_kernel<<<(N + 31) / 32, 256, 0, 0>>>(t, rowptr, sorted_src, b2, out, N);
}

// round 17
// speedup vs baseline: 1.2317x; 1.0470x over previous
#include <cuda_runtime.h>
#include <cuda_bf16.h>
#include <cuda_fp16.h>
#include <math.h>

#define MAXN 50000
#define MAXE 800000
#define F1 64      // nfeat
#define F2 128     // nhid
#define F3 64      // nclass
#define EPS 1e-6f

// ---------------- packed f32x2 helpers (Blackwell FFMA2) ----------------
typedef unsigned long long u64;
__device__ __forceinline__ u64 pack2(float lo, float hi) {
    u64 r; asm("mov.b64 %0, {%1,%2};" : "=l"(r) : "f"(lo), "f"(hi)); return r;
}
__device__ __forceinline__ u64 fma2(u64 a, u64 b, u64 c) {
    u64 d; asm("fma.rn.f32x2 %0, %1, %2, %3;" : "=l"(d) : "l"(a), "l"(b), "l"(c)); return d;
}
__device__ __forceinline__ float2 unpack2(u64 v) {
    float2 f; asm("mov.b64 {%0,%1}, %2;" : "=f"(f.x), "=f"(f.y) : "l"(v)); return f;
}

// ---------------- scratch (no allocation allowed) ----------------
__device__ __align__(16) __half g_xh[MAXN * F1];    // 6.4 MB: x in fp16
__device__ __align__(16) __half g_t[MAXN * F3];     // 6.4 MB: relu(h)@W2 in fp16
__device__ int g_counts[MAXN];                       // zero-init; self-zeroing per call
__device__ int g_rowptr[MAXN + 1];
__device__ int g_aggs[64];                           // scan block aggregates
__device__ int g_flags[64];                          // zero-init; self-resetting
__device__ int g_done[1];                            // zero-init; self-resetting
__device__ __align__(4) unsigned char g_rank[MAXE];  // edge rank within dst bucket (<256)
__device__ int g_sorted_src[MAXE];                   // src ids grouped by dst

// ================= hist + x->fp16 convert (E == N*F1/4 == 800000) =================
__global__ void hist_convert_kernel(const int* __restrict__ dst, int* __restrict__ counts,
                                    unsigned char* __restrict__ rank,
                                    const float* __restrict__ x, __half* __restrict__ xh,
                                    int E, int total4)
{
    int i = blockIdx.x * blockDim.x + threadIdx.x;
    if (i < E)
        rank[i] = (unsigned char)atomicAdd(counts + __ldg(dst + i), 1);
    if (i < total4) {
        float4 v = ((const float4*)x)[i];
        __half2 p0 = __floats2half2_rn(v.x, v.y);
        __half2 p1 = __floats2half2_rn(v.z, v.w);
        uint2 packed;
        packed.x = *(unsigned int*)&p0;
        packed.y = *(unsigned int*)&p1;
        ((uint2*)xh)[i] = packed;
    }
}

// ================= one-pass scan (decoupled aggregate lookback) =================
__global__ void scan_kernel(int* __restrict__ counts, int* __restrict__ rowptr,
                            int* __restrict__ aggs, int* __restrict__ flags,
                            int* __restrict__ done, int N, int E)
{
    __shared__ int s[256];
    __shared__ int s2[64];
    __shared__ int block_prefix;
    int b = blockIdx.x, t = threadIdx.x;
    int base = b * 1024 + t * 4;
    int v[4]; int sum = 0;
    #pragma unroll
    for (int j = 0; j < 4; j++) {
        v[j] = (base + j < N) ? counts[base + j] : 0;
        if (base + j < N) counts[base + j] = 0;
        sum += v[j];
    }
    s[t] = sum;
    if (t < 64) s2[t] = 0;
    __syncthreads();
    #pragma unroll
    for (int off = 1; off < 256; off <<= 1) {
        int x = (t >= off) ? s[t - off] : 0;
        __syncthreads();
        s[t] += x;
        __syncthreads();
    }
    int run = s[t] - sum;

    if (t == 255) {
        aggs[b] = s[255];
        __threadfence();
        atomicExch(flags + b, 1);
    }
    int pre = 0;
    if (t < b) {
        while (atomicAdd(flags + t, 0) == 0) { }
        __threadfence();
        pre = atomicAdd(aggs + t, 0);
    }
    __syncthreads();
    if (t < b) s2[t] = pre;
    __syncthreads();
    if (t == 0) {
        int p = 0;
        #pragma unroll
        for (int i = 0; i < 64; i++) p += s2[i];
        block_prefix = p;
    }
    __syncthreads();

    run += block_prefix;
    #pragma unroll
    for (int j = 0; j < 4; j++) {
        if (base + j < N) rowptr[base + j] = run;
        run += v[j];
    }
    if (b == 0 && t == 0) rowptr[N] = E;

    if (t == 0) {
        int d = atomicAdd(done, 1);
        if (d == gridDim.x - 1) {
            for (int i = 0; i < gridDim.x; i++) flags[i] = 0;
            *done = 0;
        }
    }
}

// ATOMIC-FREE scatter: position = rowptr[dst] + rank. 4 edges/thread.
__global__ void scatter_kernel(const int* __restrict__ src, const int* __restrict__ dst,
                               const int* __restrict__ rowptr,
                               const unsigned char* __restrict__ rank,
                               int* __restrict__ sorted_src, int E)
{
    int i0 = (blockIdx.x * blockDim.x + threadIdx.x) * 4;
    if (i0 + 3 < E) {
        int4 d = *(const int4*)(dst + i0);
        int4 s = *(const int4*)(src + i0);
        uchar4 r = *(const uchar4*)(rank + i0);
        sorted_src[__ldg(rowptr + d.x) + r.x] = s.x;
        sorted_src[__ldg(rowptr + d.y) + r.y] = s.y;
        sorted_src[__ldg(rowptr + d.z) + r.z] = s.z;
        sorted_src[__ldg(rowptr + d.w) + r.w] = s.w;
    } else {
        for (int i = i0; i < E; i++)
            sorted_src[__ldg(rowptr + __ldg(dst + i)) + rank[i]] = __ldg(src + i);
    }
}

// ================= Fused: gather-1 + GEMM1 + relu + GEMM2 =================
// 64-node tile, 48 KB smem, k-pair GEMM loops (R15 winner). Gather now
// accumulates in fp16 HADD2 (4 instr/edge vs 16) -> ~3x fewer gather instrs.
__global__ __launch_bounds__(256, 4) void fused12_kernel(const __half* __restrict__ xh,
                                                         const int* __restrict__ rowptr,
                                                         const int* __restrict__ sorted_src,
                                                         const float* __restrict__ W1,
                                                         const float* __restrict__ b1,
                                                         const float* __restrict__ W2,
                                                         __half* __restrict__ t,
                                                         int N)
{
    __shared__ float sbuf[64 * 128 + 64 * 64];   // 48 KB
    float (*Ws)[128] = (float(*)[128])sbuf;                  // W1, then Hs
    float (*As)[64]  = (float(*)[64])(sbuf + 64 * 128);      // mean tile, then W2 chunks

    int tid = threadIdx.x;
    int node0 = blockIdx.x * 64;
    int wid = tid >> 5, lane = tid & 31;
    int grp = lane >> 3, sl = lane & 7;          // 4 groups of 8 lanes

    // ---- A: load W1 (2048 float4, 8/thread) ----
    #pragma unroll
    for (int i = 0; i < 8; i++) {
        int lin = tid + i * 256;
        ((float4*)Ws)[lin] = ((const float4*)W1)[lin];
    }

    // ---- A: gather means. 2 passes x (8 warps x 4 rows) = 64 rows ----
    const uint4* x4 = (const uint4*)xh;          // 8 uint4 per 64-half row
    #pragma unroll
    for (int pass = 0; pass < 2; pass++) {
        int row = pass * 32 + wid * 4 + grp;
        int node = node0 + row;
        __half2 hacc[4];
        #pragma unroll
        for (int i = 0; i < 4; i++) hacc[i] = __floats2half2_rn(0.f, 0.f);
        int beg = 0, end = 0;
        if (node < N) { beg = __ldg(rowptr + node); end = __ldg(rowptr + node + 1); }
        for (int e = beg; e < end; e += 4) {
            int s[4];
            #pragma unroll
            for (int j = 0; j < 4; j++)
                s[j] = __ldg(sorted_src + min(e + j, end - 1));
            uint4 raw[4];
            #pragma unroll
            for (int j = 0; j < 4; j++)
                raw[j] = x4[s[j] * 8 + sl];
            #pragma unroll
            for (int j = 0; j < 4; j++)
                if (e + j < end) {
                    hacc[0] = __hadd2(hacc[0], *(__half2*)&raw[j].x);
                    hacc[1] = __hadd2(hacc[1], *(__half2*)&raw[j].y);
                    hacc[2] = __hadd2(hacc[2], *(__half2*)&raw[j].z);
                    hacc[3] = __hadd2(hacc[3], *(__half2*)&raw[j].w);
                }
        }
        float inv = 1.0f / ((float)(end - beg) + EPS);
        float2 f0 = __half22float2(hacc[0]);
        float2 f1 = __half22float2(hacc[1]);
        float2 f2 = __half22float2(hacc[2]);
        float2 f3 = __half22float2(hacc[3]);
        *(float4*)&As[row][sl * 8]     = make_float4(f0.x * inv, f0.y * inv, f1.x * inv, f1.y * inv);
        *(float4*)&As[row][sl * 8 + 4] = make_float4(f2.x * inv, f2.y * inv, f3.x * inv, f3.y * inv);
    }
    __syncthreads();

    // ---- B: GEMM1 (64x128), 8 rows x 4 cols/thread, k-pair ----
    int tx = tid & 31, ty = tid >> 5;
    int col0 = tx * 4, row0 = ty * 8;
    float4 bias = *(const float4*)(b1 + col0);
    u64 accL[8], accH[8];
    u64 biasL = pack2(bias.x, bias.y), biasH = pack2(bias.z, bias.w);
    #pragma unroll
    for (int r = 0; r < 8; r++) { accL[r] = biasL; accH[r] = biasH; }

    #pragma unroll 2
    for (int k2 = 0; k2 < 64; k2 += 2) {
        float4 w0 = *(float4*)&Ws[k2][col0];
        float4 w1 = *(float4*)&Ws[k2 + 1][col0];
        u64 w0L = pack2(w0.x, w0.y), w0H = pack2(w0.z, w0.w);
        u64 w1L = pack2(w1.x, w1.y), w1H = pack2(w1.z, w1.w);
        #pragma unroll
        for (int r = 0; r < 8; r++) {
            float2 m2 = *(float2*)&As[row0 + r][k2];   // broadcast, 1 wf / 2 k
            u64 mm0 = pack2(m2.x, m2.x);
            accL[r] = fma2(mm0, w0L, accL[r]);
            accH[r] = fma2(mm0, w0H, accH[r]);
            u64 mm1 = pack2(m2.y, m2.y);
            accL[r] = fma2(mm1, w1L, accL[r]);
            accH[r] = fma2(mm1, w1H, accH[r]);
        }
    }
    __syncthreads();     // S1: everyone done reading Ws/As

    // ---- C: relu -> Hs (Ws storage); load W2 chunk 0 into As ----
    #pragma unroll
    for (int r = 0; r < 8; r++) {
        float2 lo = unpack2(accL[r]), hi = unpack2(accH[r]);
        float4 o;
        o.x = fmaxf(lo.x, 0.f);
        o.y = fmaxf(lo.y, 0.f);
        o.z = fmaxf(hi.x, 0.f);
        o.w = fmaxf(hi.y, 0.f);
        *(float4*)&Ws[row0 + r][col0] = o;
    }
    #pragma unroll
    for (int i = 0; i < 4; i++) {
        int lin = tid + i * 256;
        ((float4*)As)[lin] = ((const float4*)W2)[lin];          // chunk 0
    }

    int tx2 = tid & 15, ty2 = tid >> 4;
    int c0 = tx2 * 4, r0 = ty2 * 4;
    u64 acc2L[4], acc2H[4];
    u64 zz = pack2(0.f, 0.f);
    #pragma unroll
    for (int r = 0; r < 4; r++) { acc2L[r] = zz; acc2H[r] = zz; }

    #pragma unroll
    for (int c = 0; c < 2; c++) {
        if (c == 1) {
            __syncthreads();     // S3: chunk-0 reads done
            #pragma unroll
            for (int i = 0; i < 4; i++) {
                int lin = tid + i * 256;
                ((float4*)As)[lin] = ((const float4*)W2)[1024 + lin];   // chunk 1
            }
        }
        __syncthreads();         // S2 / S4
        #pragma unroll 2
        for (int k2 = 0; k2 < 64; k2 += 2) {
            float4 w0 = *(float4*)&As[k2][c0];
            float4 w1 = *(float4*)&As[k2 + 1][c0];
            u64 w0L = pack2(w0.x, w0.y), w0H = pack2(w0.z, w0.w);
            u64 w1L = pack2(w1.x, w1.y), w1H = pack2(w1.z, w1.w);
            #pragma unroll
            for (int r = 0; r < 4; r++) {
                float2 m2 = *(float2*)&Ws[r0 + r][c * 64 + k2];
                u64 mm0 = pack2(m2.x, m2.x);
                acc2L[r] = fma2(mm0, w0L, acc2L[r]);
                acc2H[r] = fma2(mm0, w0H, acc2H[r]);
                u64 mm1 = pack2(m2.y, m2.y);
                acc2L[r] = fma2(mm1, w1L, acc2L[r]);
                acc2H[r] = fma2(mm1, w1H, acc2H[r]);
            }
        }
    }

    #pragma unroll
    for (int r = 0; r < 4; r++) {
        int node = node0 + r0 + r;
        if (node < N) {
            float2 lo = unpack2(acc2L[r]), hi = unpack2(acc2H[r]);
            __half2 p0 = __floats2half2_rn(lo.x, lo.y);
            __half2 p1 = __floats2half2_rn(hi.x, hi.y);
            uint2 packed;
            packed.x = *(unsigned int*)&p0;
            packed.y = *(unsigned int*)&p1;
            ((uint2*)t)[node * 16 + tx2] = packed;   // 16 uint2 per 64-half row
        }
    }
}

// ================= gather-2 (fp16 t, HADD2 accum) + bias + log_softmax =================
__global__ __launch_bounds__(256) void gather2_final_kernel(const __half* __restrict__ t,
                                                            const int* __restrict__ rowptr,
                                                            const int* __restrict__ sorted_src,
                                                            const float* __restrict__ b2,
                                                            float* __restrict__ out,
                                                            int N)
{
    int tid = threadIdx.x;
    int wid = tid >> 5, lane = tid & 31;
    int grp = lane >> 3, sl = lane & 7;
    int node = blockIdx.x * 32 + wid * 4 + grp;
    if (node >= N) return;

    const uint4* t4 = (const uint4*)t;   // 8 uint4 per 64-half row

    int beg = __ldg(rowptr + node);
    int end = __ldg(rowptr + node + 1);
    __half2 hacc[4];
    #pragma unroll
    for (int i = 0; i < 4; i++) hacc[i] = __floats2half2_rn(0.f, 0.f);
    for (int e = beg; e < end; e += 4) {
        int s[4];
        #pragma unroll
        for (int j = 0; j < 4; j++)
            s[j] = __ldg(sorted_src + min(e + j, end - 1));
        uint4 raw[4];
        #pragma unroll
        for (int j = 0; j < 4; j++)
            raw[j] = t4[s[j] * 8 + sl];
        #pragma unroll
        for (int j = 0; j < 4; j++)
            if (e + j < end) {
                hacc[0] = __hadd2(hacc[0], *(__half2*)&raw[j].x);
                hacc[1] = __hadd2(hacc[1], *(__half2*)&raw[j].y);
                hacc[2] = __hadd2(hacc[2], *(__half2*)&raw[j].z);
                hacc[3] = __hadd2(hacc[3], *(__half2*)&raw[j].w);
            }
    }
    float inv = 1.0f / ((float)(end - beg) + EPS);
    float2 f0 = __half22float2(hacc[0]);
    float2 f1 = __half22float2(hacc[1]);
    float2 f2 = __half22float2(hacc[2]);
    float2 f3 = __half22float2(hacc[3]);
    float4 bb0 = ((const float4*)b2)[sl * 2];
    float4 bb1 = ((const float4*)b2)[sl * 2 + 1];
    float v[8];
    v[0] = f0.x * inv + bb0.x;
    v[1] = f0.y * inv + bb0.y;
    v[2] = f1.x * inv + bb0.z;
    v[3] = f1.y * inv + bb0.w;
    v[4] = f2.x * inv + bb1.x;
    v[5] = f2.y * inv + bb1.y;
    v[6] = f3.x * inv + bb1.z;
    v[7] = f3.y * inv + bb1.w;

    float m = v[0];
    #pragma unroll
    for (int i = 1; i < 8; i++) m = fmaxf(m, v[i]);
    #pragma unroll
    for (int o = 4; o > 0; o >>= 1)
        m = fmaxf(m, __shfl_xor_sync(0xffffffffu, m, o));
    float s = 0.f;
    #pragma unroll
    for (int i = 0; i < 8; i++) s += expf(v[i] - m);
    #pragma unroll
    for (int o = 4; o > 0; o >>= 1)
        s += __shfl_xor_sync(0xffffffffu, s, o);
    float l = m + logf(s);

    float4 o0 = make_float4(v[0] - l, v[1] - l, v[2] - l, v[3] - l);
    float4 o1 = make_float4(v[4] - l, v[5] - l, v[6] - l, v[7] - l);
    ((float4*)out)[node * 16 + sl * 2]     = o0;
    ((float4*)out)[node * 16 + sl * 2 + 1] = o1;
}

extern "C" void kernel_launch(void* const* d_in, const int* in_sizes, int n_in,
                              void* d_out, int out_size)
{
    const float* x   = (const float*)d_in[0];
    const int*   src = (const int*)d_in[1];
    const int*   dst = (const int*)d_in[2];
    const float* W1  = (const float*)d_in[3];
    const float* b1  = (const float*)d_in[4];
    const float* W2  = (const float*)d_in[5];
    const float* b2  = (const float*)d_in[6];
    float* out = (float*)d_out;

    int N = in_sizes[0] / F1;
    int E = in_sizes[1];

    __half *t, *xh;
    int *counts, *rowptr, *aggs, *flags, *done, *sorted_src;
    unsigned char *rank;
    cudaGetSymbolAddress((void**)&t, g_t);
    cudaGetSymbolAddress((void**)&xh, g_xh);
    cudaGetSymbolAddress((void**)&counts, g_counts);
    cudaGetSymbolAddress((void**)&rowptr, g_rowptr);
    cudaGetSymbolAddress((void**)&aggs, g_aggs);
    cudaGetSymbolAddress((void**)&flags, g_flags);
    cudaGetSymbolAddress((void**)&done, g_done);
    cudaGetSymbolAddress((void**)&rank, g_rank);
    cudaGetSymbolAddress((void**)&sorted_src, g_sorted_src);

    // ---- 1: hist + x->fp16 (counts zero on entry; scan re-zeroes) ----
    int total4 = (N * F1) / 4;
    int w = max(E, total4);
    hist_convert_kernel<<<(w + 255) / 256, 256, 0, 0>>>(dst, counts, rank, x, xh, E, total4);

    // ---- 2: one-pass scan -> final rowptr ----
    int nb = (N + 1023) / 1024;
    scan_kernel<<<nb, 256, 0, 0>>>(counts, rowptr, aggs, flags, done, N, E);

    // ---- 3: atomic-free scatter ----
    int et = (E + 3) / 4;
    scatter_kernel<<<(et + 255) / 256, 256, 0, 0>>>(src, dst, rowptr, rank, sorted_src, E);

    // ---- 4: gather(mean, fp16) -> W1+b1+relu -> @W2 -> t (fp16), 64-node tiles ----
    fused12_kernel<<<(N + 63) / 64, 256, 0, 0>>>(xh, rowptr, sorted_src, W1, b1, W2, t, N);

    // ---- 5: gather(mean, fp16) + b2 + log_softmax ----
    gather2_final_kernel<<<(N + 31) / 32, 256, 0, 0>>>(t, rowptr, sorted_src, b2, out, N);
}